// round 6
// baseline (speedup 1.0000x reference)
#include <cuda_runtime.h>
#include <cstdint>
#include <math.h>

#define C_DIM 256
#define NTOK 2048          // 64 * 32 tokens per side per batch
#define SB_COUNT 16        // side(2) * batch(8)

// ---------------- scratch (static device globals; no allocation) ----------------
__device__ float g_q[SB_COUNT * NTOK * C_DIM];
__device__ float g_k[SB_COUNT * NTOK * C_DIM];
__device__ float g_v[SB_COUNT * NTOK * C_DIM];
__device__ float g_attT[SB_COUNT * C_DIM * NTOK];       // attention ctx, transposed [sb][c][n]
__device__ float g_ctxT[SB_COUNT * C_DIM * NTOK];       // out-proj result, transposed [sb][c][n]
__device__ float g_inwT[C_DIM * 768];                   // in_w^T  (tf32-rounded)
__device__ float g_outwT[C_DIM * C_DIM];                // out_w^T (tf32-rounded)
__device__ float g_projwT[1024 * C_DIM];                // proj_w^T(tf32-rounded)

// ---------------- helpers ----------------
__device__ __forceinline__ uint32_t f2tf(float x) {
    uint32_t u; asm("cvt.rna.tf32.f32 %0, %1;" : "=r"(u) : "f"(x)); return u;
}
__device__ __forceinline__ void mma8(float* c, const uint32_t* a, const uint32_t* b) {
    asm volatile("mma.sync.aligned.m16n8k8.row.col.f32.tf32.tf32.f32 "
        "{%0,%1,%2,%3}, {%4,%5,%6,%7}, {%8,%9}, {%0,%1,%2,%3};"
        : "+f"(c[0]), "+f"(c[1]), "+f"(c[2]), "+f"(c[3])
        : "r"(a[0]), "r"(a[1]), "r"(a[2]), "r"(a[3]), "r"(b[0]), "r"(b[1]));
}
__device__ __forceinline__ uint32_t csel(uint4 v, int c) {
    return c == 0 ? v.x : c == 1 ? v.y : c == 2 ? v.z : v.w;
}

// ---- fragment-major smem addressing (BK=16, split into 2 k-blocks of 8) ----
// A value (row r, k): mt=r>>4, q=r&7, h=(r>>3)&1; kb=k>>3, kk=k&7, tq=kk&3, kh=kk>>2
__device__ __forceinline__ int a_addr(int r, int k) {
    int mt = r >> 4, q = r & 7, h = (r >> 3) & 1;
    int kb = k >> 3, kk = k & 7, tq = kk & 3, kh = kk >> 2;
    return (kb * 8 + mt) * 128 + (q * 4 + (tq ^ (q >> 1))) * 4
         + ((h + 2 * kh) ^ ((mt & 1) * 2) ^ kb);
}
// B value (col n, k): njp = BN/16 tiles per k-block
__device__ __forceinline__ int b_addr(int n, int k, int njp) {
    int jp = n >> 4, q = n & 7, jh = (n >> 3) & 1;
    int kb = k >> 3, kk = k & 7, tq = kk & 3, s = kk >> 2;
    return (kb * njp + jp) * 128 + (q * 4 + (tq ^ (q >> 1))) * 4
         + ((s * 2 + jh) ^ ((jp & 1) * 2) ^ kb);
}
// loads: lane unit
__device__ __forceinline__ int lane_unit(int lane) {
    int q = lane >> 2, tq = lane & 3;
    return q * 4 + (tq ^ (q >> 1));
}
__device__ __forceinline__ void load_afrag(uint32_t* af, const uint32_t* As,
                                           int mt, int kb, int lunit, int sw) {
    uint4 v = *(const uint4*)&As[(kb * 8 + mt) * 128 + lunit * 4];
    af[0] = csel(v, 0 ^ sw); af[1] = csel(v, 1 ^ sw);
    af[2] = csel(v, 2 ^ sw); af[3] = csel(v, 3 ^ sw);
}
__device__ __forceinline__ void load_bfrag(uint32_t (*bf)[2], const uint32_t* Bs,
                                           int jp, int kb, int njp, int lunit, int sw) {
    uint4 v = *(const uint4*)&Bs[(kb * njp + jp) * 128 + lunit * 4];
    bf[0][0] = csel(v, 0 ^ sw); bf[1][0] = csel(v, 1 ^ sw);
    bf[0][1] = csel(v, 2 ^ sw); bf[1][1] = csel(v, 3 ^ sw);
}

// ---------------- K0: transpose + tf32-round weights ----------------
__global__ void transpose_weights(const float* __restrict__ in_w,
                                  const float* __restrict__ out_w,
                                  const float* __restrict__ proj_w) {
    int i = blockIdx.x * blockDim.x + threadIdx.x;
    if (i < 768 * 256) { int co = i >> 8;  int c = i & 255;  g_inwT[c * 768 + co]  = __uint_as_float(f2tf(in_w[i])); }
    if (i < 256 * 256) { int co = i >> 8;  int c = i & 255;  g_outwT[c * 256 + co] = __uint_as_float(f2tf(out_w[i])); }
    if (i < 256 * 1024){ int co = i >> 10; int j = i & 1023; g_projwT[j * 256 + co] = __uint_as_float(f2tf(proj_w[i])); }
}

// ---------------- K1: QKV GEMM (tf32 mma, fragment-major smem) ----------------
// BM=128 BN=128 BK=16, 256 thr, warp tile 64x32
__global__ void __launch_bounds__(256) qkv_gemm(const float* __restrict__ feat,
                                                const float* __restrict__ in_b) {
    const int co0 = blockIdx.x * 128;
    const int m0  = blockIdx.y * 128;
    const int sb  = blockIdx.z;
    const int side = sb >> 3, b = sb & 7;
    const bool is_q = (co0 < 256);
    const float* featB = feat + (size_t)b * (C_DIM * 4096);

    __shared__ uint32_t As[2048];
    __shared__ uint32_t Bs[2048];

    const int t = threadIdx.x;
    const int w = t >> 5, lane = t & 31, quad = lane >> 2, tq = lane & 3;
    const int mw = (w & 1) * 64, nw = (w >> 1) * 32;
    const int lunit = lane_unit(lane);

    float acc[4][4][4];
#pragma unroll
    for (int i = 0; i < 4; ++i)
#pragma unroll
        for (int j = 0; j < 4; ++j)
#pragma unroll
            for (int p = 0; p < 4; ++p) acc[i][j][p] = 0.0f;

    const int mm = t & 127;
    const int m  = m0 + mm;
    const int yq = m >> 5, xq = m & 31;
    const int colg = is_q ? (side ? 32 + xq : xq) : (side ? 31 - xq : 63 - xq);
    const int aoff = yq * 64 + colg;
    const int jj = t & 127;
    const int kb0 = t >> 7;   // 0 or 1; this thread fills k = kb0 + 2*i

    float ra[8], rb[8];
#pragma unroll
    for (int i = 0; i < 8; ++i) {
        ra[i] = featB[(size_t)(kb0 + 2 * i) * 4096 + aoff];
        rb[i] = g_inwT[(kb0 + 2 * i) * 768 + co0 + jj];
    }

    for (int kt = 0; kt < 16; ++kt) {
#pragma unroll
        for (int i = 0; i < 8; ++i) {
            int k = kb0 + 2 * i;
            As[a_addr(mm, k)] = f2tf(ra[i]);
            Bs[b_addr(jj, k, 8)] = __float_as_uint(rb[i]);
        }
        __syncthreads();
        if (kt < 15) {
            const int c0 = (kt + 1) * 16;
#pragma unroll
            for (int i = 0; i < 8; ++i) {
                ra[i] = featB[(size_t)(c0 + kb0 + 2 * i) * 4096 + aoff];
                rb[i] = g_inwT[(c0 + kb0 + 2 * i) * 768 + co0 + jj];
            }
        }
#pragma unroll
        for (int kb = 0; kb < 2; ++kb) {
            uint32_t af[4][4], bf[4][2];
#pragma unroll
            for (int i = 0; i < 4; ++i)
                load_afrag(af[i], As, (mw >> 4) + i, kb, lunit, ((i & 1) * 2) ^ kb);
#pragma unroll
            for (int jp = 0; jp < 2; ++jp)
                load_bfrag(&bf[2 * jp], Bs, (nw >> 4) + jp, kb, 8, lunit, ((jp & 1) * 2) ^ kb);
#pragma unroll
            for (int i = 0; i < 4; ++i)
#pragma unroll
                for (int j = 0; j < 4; ++j)
                    mma8(acc[i][j], af[i], bf[j]);
        }
        __syncthreads();
    }

    const size_t rowbase = (size_t)sb * NTOK;
#pragma unroll
    for (int i = 0; i < 4; ++i) {
        int r0 = m0 + mw + i * 16 + quad;
#pragma unroll
        for (int j = 0; j < 4; ++j) {
            int co = co0 + nw + j * 8 + tq * 2;
            float b0 = in_b[co], b1 = in_b[co + 1];
            float* dst = (co < 256) ? g_q : ((co < 512) ? g_k : g_v);
            int cl = co & 255;
            float2 v0 = make_float2(acc[i][j][0] + b0, acc[i][j][1] + b1);
            float2 v1 = make_float2(acc[i][j][2] + b0, acc[i][j][3] + b1);
            *(float2*)&dst[(rowbase + r0) * C_DIM + cl]     = v0;
            *(float2*)&dst[(rowbase + r0 + 8) * C_DIM + cl] = v1;
        }
    }
}

// ---------------- K2: sparse attention, writes transposed g_attT ----------------
__global__ void __launch_bounds__(256) attn_kernel() {
    const int wp   = threadIdx.x >> 5;
    const int lane = threadIdx.x & 31;
    const int wgid = blockIdx.x * 8 + wp;
    const int n  = wgid & 2047;
    const int hd = (wgid >> 11) & 3;
    const int sb = wgid >> 13;
    const int y = n >> 5, x = n & 31;

    __shared__ float st[64][9];

    const float* qb = g_q + ((size_t)sb * NTOK + n) * C_DIM + hd * 64;
    const float q0 = qb[lane];
    const float q1 = qb[lane + 32];

    const int ody[13] = {0, 0, 0, 0, 0, -1, -1, -1, 1, 1, 1, -2, 2};
    const int odx[13] = {0,-1, 1,-2, 2,  0, -1,  1, 0,-1, 1,  0, 0};
    float sc[13];
    int   midx[13];

#pragma unroll
    for (int i = 0; i < 13; ++i) {
        int yy = y + ody[i], xx = x + odx[i];
        bool valid = (yy >= 0) && (yy < 64) && (xx >= 0) && (xx < 32);
        int mm = valid ? (yy * 32 + xx) : n;
        midx[i] = valid ? mm : -1;
        const float* kb = g_k + ((size_t)sb * NTOK + mm) * C_DIM + hd * 64;
        float s = q0 * kb[lane] + q1 * kb[lane + 32];
#pragma unroll
        for (int o = 16; o > 0; o >>= 1) s += __shfl_xor_sync(0xffffffffu, s, o);
        sc[i] = valid ? s * 0.125f : -1e30f;
    }

    float mx = -1e30f;
#pragma unroll
    for (int i = 0; i < 13; ++i) mx = fmaxf(mx, sc[i]);
    float ssum = 0.0f;
#pragma unroll
    for (int i = 0; i < 13; ++i) {
        sc[i] = (midx[i] >= 0) ? __expf(sc[i] - mx) : 0.0f;
        ssum += sc[i];
    }
    const float inv = 1.0f / ssum;

    float a0 = 0.0f, a1 = 0.0f;
#pragma unroll
    for (int i = 0; i < 13; ++i) {
        if (midx[i] >= 0) {
            const float* vb = g_v + ((size_t)sb * NTOK + midx[i]) * C_DIM + hd * 64;
            float wgt = sc[i] * inv;
            a0 += wgt * vb[lane];
            a1 += wgt * vb[lane + 32];
        }
    }

    // stage & transpose: st[channel d][token j]
    st[lane][wp]      = a0;
    st[lane + 32][wp] = a1;
    __syncthreads();

    const int base = blockIdx.x * 8;
    const int n0  = base & 2047;
    const int hdb = (base >> 11) & 3;
    const int sbb = base >> 13;
#pragma unroll
    for (int v = 0; v < 2; ++v) {
        int idx = threadIdx.x + 256 * v;
        int d = idx >> 3, j = idx & 7;
        g_attT[((size_t)sbb * C_DIM + hdb * 64 + d) * NTOK + n0 + j] = st[d][j];
    }
}

// ---------------- K3: out-proj GEMM (tf32 mma, fragment-major), writes g_ctxT ----------------
__global__ void __launch_bounds__(256) outproj_gemm(const float* __restrict__ out_b) {
    const int co0 = blockIdx.x * 128;
    const int m0  = blockIdx.y * 128;
    const int sb  = blockIdx.z;

    __shared__ uint32_t As[2048];
    __shared__ uint32_t Bs[2048];

    const int t = threadIdx.x;
    const int w = t >> 5, lane = t & 31, quad = lane >> 2, tq = lane & 3;
    const int mw = (w & 1) * 64, nw = (w >> 1) * 32;
    const int lunit = lane_unit(lane);

    float acc[4][4][4];
#pragma unroll
    for (int i = 0; i < 4; ++i)
#pragma unroll
        for (int j = 0; j < 4; ++j)
#pragma unroll
            for (int p = 0; p < 4; ++p) acc[i][j][p] = 0.0f;

    const int mm = t & 127;
    const int jj = t & 127;
    const int kb0 = t >> 7;
    const float* attTB = g_attT + (size_t)sb * C_DIM * NTOK;

    float ra[8], rb[8];
#pragma unroll
    for (int i = 0; i < 8; ++i) {
        ra[i] = attTB[(size_t)(kb0 + 2 * i) * NTOK + m0 + mm];
        rb[i] = g_outwT[(kb0 + 2 * i) * 256 + co0 + jj];
    }

    for (int kt = 0; kt < 16; ++kt) {
#pragma unroll
        for (int i = 0; i < 8; ++i) {
            int k = kb0 + 2 * i;
            As[a_addr(mm, k)] = f2tf(ra[i]);
            Bs[b_addr(jj, k, 8)] = __float_as_uint(rb[i]);
        }
        __syncthreads();
        if (kt < 15) {
            const int c0 = (kt + 1) * 16;
#pragma unroll
            for (int i = 0; i < 8; ++i) {
                ra[i] = attTB[(size_t)(c0 + kb0 + 2 * i) * NTOK + m0 + mm];
                rb[i] = g_outwT[(c0 + kb0 + 2 * i) * 256 + co0 + jj];
            }
        }
#pragma unroll
        for (int kb = 0; kb < 2; ++kb) {
            uint32_t af[4][4], bf[4][2];
#pragma unroll
            for (int i = 0; i < 4; ++i)
                load_afrag(af[i], As, (mw >> 4) + i, kb, lunit, ((i & 1) * 2) ^ kb);
#pragma unroll
            for (int jp = 0; jp < 2; ++jp)
                load_bfrag(&bf[2 * jp], Bs, (nw >> 4) + jp, kb, 8, lunit, ((jp & 1) * 2) ^ kb);
#pragma unroll
            for (int i = 0; i < 4; ++i)
#pragma unroll
                for (int j = 0; j < 4; ++j)
                    mma8(acc[i][j], af[i], bf[j]);
        }
        __syncthreads();
    }

#pragma unroll
    for (int i = 0; i < 4; ++i) {
        int r0 = m0 + mw + i * 16 + quad;
#pragma unroll
        for (int j = 0; j < 4; ++j) {
            int co = co0 + nw + j * 8 + tq * 2;
            float b0 = out_b[co], b1 = out_b[co + 1];
            float* base = g_ctxT + (size_t)sb * C_DIM * NTOK;
            base[(size_t)co * NTOK + r0]           = acc[i][j][0] + b0;
            base[(size_t)(co + 1) * NTOK + r0]     = acc[i][j][1] + b1;
            base[(size_t)co * NTOK + r0 + 8]       = acc[i][j][2] + b0;
            base[(size_t)(co + 1) * NTOK + r0 + 8] = acc[i][j][3] + b1;
        }
    }
}

// ---------------- K4: fused asym-concat + proj (tf32 mma) + LayerNorm + ReLU ----------------
// BM=128, BN=256 (full row), BK=16, 512 thr, warp tile 32x64
__global__ void __launch_bounds__(512) fused_proj_ln(const float* __restrict__ feat,
                                                     const float* __restrict__ proj_b,
                                                     const float* __restrict__ ln_g,
                                                     const float* __restrict__ ln_b,
                                                     float* __restrict__ out) {
    const int m0 = blockIdx.y * 128;
    const int sb = blockIdx.z;
    const int side = sb >> 3, b = sb & 7;
    const float* featB = feat + (size_t)b * (C_DIM * 4096);
    const float* ctxTB = g_ctxT + (size_t)sb * C_DIM * NTOK;

    __shared__ uint32_t As[2048];
    __shared__ uint32_t Bs[4096];
    __shared__ float2 red[128][4];

    const int t = threadIdx.x;
    const int w = t >> 5, lane = t & 31, quad = lane >> 2, tq = lane & 3;
    const int wm = w & 3, nwi = w >> 2;
    const int mw = wm * 32, nwcol = nwi * 64;
    const int lunit = lane_unit(lane);

    float acc[2][8][4];
#pragma unroll
    for (int i = 0; i < 2; ++i)
#pragma unroll
        for (int j = 0; j < 8; ++j)
#pragma unroll
            for (int p = 0; p < 4; ++p) acc[i][j][p] = 0.0f;

    const int amm = t & 127, akb = t >> 7;       // fills k = akb + 4*i
    const int lm = m0 + amm;
    const int ly = lm >> 5, lx = lm & 31;
    const int qoff = ly * 64 + (side ? 32 + lx : lx);
    const int bjj = t & 255, bkb = t >> 8;       // fills k = bkb + 2*i

    float rq[4], rc[4], rb[8];

    // prefetch kt=0 (part 0: qt only)
#pragma unroll
    for (int i = 0; i < 4; ++i)
        rq[i] = featB[(size_t)(akb + 4 * i) * 4096 + qoff];
#pragma unroll
    for (int i = 0; i < 8; ++i)
        rb[i] = g_projwT[(bkb + 2 * i) * 256 + bjj];
#pragma unroll
    for (int i = 0; i < 4; ++i) rc[i] = 0.0f;

    for (int kt = 0; kt < 64; ++kt) {
        const int part = kt >> 4;
#pragma unroll
        for (int i = 0; i < 4; ++i) {
            float v;
            if (part == 0)      v = rq[i];
            else if (part == 1) v = rc[i];
            else if (part == 2) v = fabsf(rq[i] - rc[i]);
            else                v = rq[i] * rc[i];
            As[a_addr(amm, akb + 4 * i)] = f2tf(v);
        }
#pragma unroll
        for (int i = 0; i < 8; ++i)
            Bs[b_addr(bjj, bkb + 2 * i, 16)] = __float_as_uint(rb[i]);
        __syncthreads();

        if (kt < 63) {
            const int j0 = (kt + 1) * 16;
            const int np = j0 >> 8;
#pragma unroll
            for (int i = 0; i < 4; ++i) {
                int jc = (j0 + akb + 4 * i) & 255;
                if (np != 1) rq[i] = featB[(size_t)jc * 4096 + qoff];
                if (np != 0) rc[i] = ctxTB[(size_t)jc * NTOK + lm];
            }
#pragma unroll
            for (int i = 0; i < 8; ++i)
                rb[i] = g_projwT[(j0 + bkb + 2 * i) * 256 + bjj];
        }

#pragma unroll
        for (int kb = 0; kb < 2; ++kb) {
            uint32_t af[2][4], bf[8][2];
#pragma unroll
            for (int i = 0; i < 2; ++i)
                load_afrag(af[i], As, wm * 2 + i, kb, lunit, ((i & 1) * 2) ^ kb);
#pragma unroll
            for (int jp = 0; jp < 4; ++jp)
                load_bfrag(&bf[2 * jp], Bs, nwi * 4 + jp, kb, 16, lunit, ((jp & 1) * 2) ^ kb);
#pragma unroll
            for (int i = 0; i < 2; ++i)
#pragma unroll
                for (int j = 0; j < 8; ++j)
                    mma8(acc[i][j], af[i], bf[j]);
        }
        __syncthreads();
    }

    // ---- epilogue: +bias, LN(256), relu, transposed scatter ----
#pragma unroll
    for (int j = 0; j < 8; ++j) {
        int co = nwcol + j * 8 + tq * 2;
        float2 pb = *(const float2*)&proj_b[co];
#pragma unroll
        for (int i = 0; i < 2; ++i) {
            acc[i][j][0] += pb.x; acc[i][j][1] += pb.y;
            acc[i][j][2] += pb.x; acc[i][j][3] += pb.y;
        }
    }

#pragma unroll
    for (int i = 0; i < 2; ++i)
#pragma unroll
        for (int u = 0; u < 2; ++u) {
            float s1 = 0.0f, s2 = 0.0f;
#pragma unroll
            for (int j = 0; j < 8; ++j) {
                float x0 = acc[i][j][2 * u], x1 = acc[i][j][2 * u + 1];
                s1 += x0 + x1; s2 += x0 * x0 + x1 * x1;
            }
            s1 += __shfl_xor_sync(0xffffffffu, s1, 1);
            s2 += __shfl_xor_sync(0xffffffffu, s2, 1);
            s1 += __shfl_xor_sync(0xffffffffu, s1, 2);
            s2 += __shfl_xor_sync(0xffffffffu, s2, 2);
            if (tq == 0) {
                int r = mw + i * 16 + u * 8 + quad;
                red[r][nwi] = make_float2(s1, s2);
            }
        }
    __syncthreads();

#pragma unroll
    for (int i = 0; i < 2; ++i)
#pragma unroll
        for (int u = 0; u < 2; ++u) {
            int r = mw + i * 16 + u * 8 + quad;
            float s1 = 0.0f, s2 = 0.0f;
#pragma unroll
            for (int p = 0; p < 4; ++p) { float2 v = red[r][p]; s1 += v.x; s2 += v.y; }
            float mu   = s1 * (1.0f / 256.0f);
            float var  = s2 * (1.0f / 256.0f) - mu * mu;
            float rstd = rsqrtf(var + 1e-5f);

            int grow = m0 + r;
            int y = grow >> 5, x = grow & 31;
            int xg = side ? (32 + x) : x;
            size_t obase = (size_t)b * C_DIM * 4096 + y * 64 + xg;
#pragma unroll
            for (int j = 0; j < 8; ++j) {
                int co = nwcol + j * 8 + tq * 2;
                float g0 = ln_g[co], g1 = ln_g[co + 1];
                float l0 = ln_b[co], l1 = ln_b[co + 1];
                float v0 = fmaxf((acc[i][j][2 * u]     - mu) * rstd * g0 + l0, 0.0f);
                float v1 = fmaxf((acc[i][j][2 * u + 1] - mu) * rstd * g1 + l1, 0.0f);
                out[obase + (size_t)co * 4096]       = v0;
                out[obase + (size_t)(co + 1) * 4096] = v1;
            }
        }
}

// ---------------- launch ----------------
extern "C" void kernel_launch(void* const* d_in, const int* in_sizes, int n_in,
                              void* d_out, int out_size) {
    const float* feat   = (const float*)d_in[0];
    const float* in_w   = (const float*)d_in[1];
    const float* in_b   = (const float*)d_in[2];
    const float* out_w  = (const float*)d_in[3];
    const float* out_b  = (const float*)d_in[4];
    const float* proj_w = (const float*)d_in[5];
    const float* proj_b = (const float*)d_in[6];
    const float* ln_g   = (const float*)d_in[7];
    const float* ln_b   = (const float*)d_in[8];
    float* out = (float*)d_out;

    transpose_weights<<<1024, 256>>>(in_w, out_w, proj_w);
    qkv_gemm<<<dim3(6, 16, 16), 256>>>(feat, in_b);
    attn_kernel<<<16384, 256>>>();
    outproj_gemm<<<dim3(2, 16, 16), 256>>>(out_b);
    fused_proj_ln<<<dim3(1, 16, 16), 512>>>(feat, proj_b, ln_g, ln_b, out);
}

// round 8
// speedup vs baseline: 1.0675x; 1.0675x over previous
#include <cuda_runtime.h>
#include <cstdint>
#include <math.h>

#define C_DIM 256
#define NTOK 2048          // 64 * 32 tokens per side per batch
#define SB_COUNT 16        // side(2) * batch(8)

// ---------------- scratch (static device globals; no allocation) ----------------
__device__ float g_featR[8 * C_DIM * 4096];             // tf32-rounded feat (same layout)
__device__ float g_q[SB_COUNT * NTOK * C_DIM];
__device__ float g_k[SB_COUNT * NTOK * C_DIM];
__device__ float g_v[SB_COUNT * NTOK * C_DIM];
__device__ float g_attT[SB_COUNT * C_DIM * NTOK];       // attention ctx, transposed + tf32-rounded
__device__ float g_ctxT[SB_COUNT * C_DIM * NTOK];       // out-proj result, transposed [sb][c][n]
__device__ float g_inwT[C_DIM * 768];                   // in_w^T  (tf32-rounded)
__device__ float g_outwT[C_DIM * C_DIM];                // out_w^T (tf32-rounded)
__device__ float g_projwT[1024 * C_DIM];                // proj_w^T(tf32-rounded)

// ---------------- helpers ----------------
__device__ __forceinline__ uint32_t f2tf(float x) {
    uint32_t u; asm("cvt.rna.tf32.f32 %0, %1;" : "=r"(u) : "f"(x)); return u;
}
__device__ __forceinline__ void mma8(float* c, const uint32_t* a, const uint32_t* b) {
    asm volatile("mma.sync.aligned.m16n8k8.row.col.f32.tf32.tf32.f32 "
        "{%0,%1,%2,%3}, {%4,%5,%6,%7}, {%8,%9}, {%0,%1,%2,%3};"
        : "+f"(c[0]), "+f"(c[1]), "+f"(c[2]), "+f"(c[3])
        : "r"(a[0]), "r"(a[1]), "r"(a[2]), "r"(a[3]), "r"(b[0]), "r"(b[1]));
}
__device__ __forceinline__ uint32_t sptr(const void* p) {
    return (uint32_t)__cvta_generic_to_shared(p);
}
#define CPA4(d, s)  asm volatile("cp.async.ca.shared.global [%0], [%1], 4;"  :: "r"(d), "l"(s))
#define CPA16(d, s) asm volatile("cp.async.cg.shared.global [%0], [%1], 16;" :: "r"(d), "l"(s))
#define CPC()  asm volatile("cp.async.commit_group;")
#define CPW1() asm volatile("cp.async.wait_group 1;")

// ---------------- K0a: transpose + tf32-round weights ----------------
__global__ void transpose_weights(const float* __restrict__ in_w,
                                  const float* __restrict__ out_w,
                                  const float* __restrict__ proj_w) {
    int i = blockIdx.x * blockDim.x + threadIdx.x;
    if (i < 768 * 256) { int co = i >> 8;  int c = i & 255;  g_inwT[c * 768 + co]  = __uint_as_float(f2tf(in_w[i])); }
    if (i < 256 * 256) { int co = i >> 8;  int c = i & 255;  g_outwT[c * 256 + co] = __uint_as_float(f2tf(out_w[i])); }
    if (i < 256 * 1024){ int co = i >> 10; int j = i & 1023; g_projwT[j * 256 + co] = __uint_as_float(f2tf(proj_w[i])); }
}

// ---------------- K0b: tf32-round feat ----------------
__global__ void round_feat(const float* __restrict__ feat) {
    int i = blockIdx.x * blockDim.x + threadIdx.x;   // float4 index
    float4 v = ((const float4*)feat)[i];
    v.x = __uint_as_float(f2tf(v.x)); v.y = __uint_as_float(f2tf(v.y));
    v.z = __uint_as_float(f2tf(v.z)); v.w = __uint_as_float(f2tf(v.w));
    ((float4*)g_featR)[i] = v;
}

// ---------------- K1: QKV GEMM (tf32 mma, 3-stage cp.async) ----------------
// BM=128 BN=128 BK=16, 256 thr, warp tile 64x32. smem stage = [16][136] words.
__global__ void __launch_bounds__(256) qkv_gemm(const float* __restrict__ in_b) {
    extern __shared__ uint32_t sm[];
    uint32_t* As = sm;              // 3 stages * 2176 words
    uint32_t* Bs = sm + 3 * 2176;

    const int co0 = blockIdx.x * 128;
    const int m0  = blockIdx.y * 128;
    const int sb  = blockIdx.z;
    const int side = sb >> 3, b = sb & 7;
    const bool is_q = (co0 < 256);
    const float* featRB = g_featR + (size_t)b * (C_DIM * 4096);

    const int t = threadIdx.x;
    const int w = t >> 5, lane = t & 31, quad = lane >> 2, tq = lane & 3;
    const int mw = (w & 1) * 64, nw = (w >> 1) * 32;

    const int mm = t & 127;
    const int m  = m0 + mm;
    const int yq = m >> 5, xq = m & 31;
    const int colg = is_q ? (side ? 32 + xq : xq) : (side ? 31 - xq : 63 - xq);
    const int aoff = yq * 64 + colg;
    const int kb0 = t >> 7;   // fills k = kb0 + 2*i

    const uint32_t abase0 = sptr(As), bbase0 = sptr(Bs);

    auto fill = [&](int s, int kt) {
        const int c0 = kt * 16;
        const uint32_t ab = abase0 + s * 8704;
        const uint32_t bb = bbase0 + s * 8704;
#pragma unroll
        for (int i = 0; i < 8; ++i) {
            int k = kb0 + 2 * i;
            CPA4(ab + (k * 136 + mm) * 4, featRB + (size_t)(c0 + k) * 4096 + aoff);
        }
#pragma unroll
        for (int i = 0; i < 2; ++i) {
            int idx = t + 256 * i;
            int k = idx >> 5, jg = idx & 31;
            CPA16(bb + (k * 136 + jg * 4) * 4, g_inwT + (c0 + k) * 768 + co0 + jg * 4);
        }
    };

    float acc[4][4][4];
#pragma unroll
    for (int i = 0; i < 4; ++i)
#pragma unroll
        for (int j = 0; j < 4; ++j)
#pragma unroll
            for (int p = 0; p < 4; ++p) acc[i][j][p] = 0.0f;

    fill(0, 0); CPC();
    fill(1, 1); CPC();

    for (int kt = 0; kt < 16; ++kt) {
        CPW1();
        __syncthreads();
        if (kt + 2 < 16) fill((kt + 2) % 3, kt + 2);
        CPC();
        const uint32_t* A = As + (kt % 3) * 2176;
        const uint32_t* B = Bs + (kt % 3) * 2176;
#pragma unroll
        for (int kb = 0; kb < 2; ++kb) {
            const int k0 = kb * 8;
            uint32_t af[4][4], bf[4][2];
#pragma unroll
            for (int i = 0; i < 4; ++i) {
                af[i][0] = A[(k0 + tq) * 136 + mw + i * 16 + quad];
                af[i][1] = A[(k0 + tq) * 136 + mw + i * 16 + quad + 8];
                af[i][2] = A[(k0 + tq + 4) * 136 + mw + i * 16 + quad];
                af[i][3] = A[(k0 + tq + 4) * 136 + mw + i * 16 + quad + 8];
            }
#pragma unroll
            for (int j = 0; j < 4; ++j) {
                bf[j][0] = B[(k0 + tq) * 136 + nw + j * 8 + quad];
                bf[j][1] = B[(k0 + tq + 4) * 136 + nw + j * 8 + quad];
            }
#pragma unroll
            for (int i = 0; i < 4; ++i)
#pragma unroll
                for (int j = 0; j < 4; ++j)
                    mma8(acc[i][j], af[i], bf[j]);
        }
    }

    const size_t rowbase = (size_t)sb * NTOK;
#pragma unroll
    for (int i = 0; i < 4; ++i) {
        int r0 = m0 + mw + i * 16 + quad;
#pragma unroll
        for (int j = 0; j < 4; ++j) {
            int co = co0 + nw + j * 8 + tq * 2;
            float b0 = in_b[co], b1 = in_b[co + 1];
            float* dst = (co < 256) ? g_q : ((co < 512) ? g_k : g_v);
            int cl = co & 255;
            float2 v0 = make_float2(acc[i][j][0] + b0, acc[i][j][1] + b1);
            float2 v1 = make_float2(acc[i][j][2] + b0, acc[i][j][3] + b1);
            *(float2*)&dst[(rowbase + r0) * C_DIM + cl]     = v0;
            *(float2*)&dst[(rowbase + r0 + 8) * C_DIM + cl] = v1;
        }
    }
}

// ---------------- K2: sparse attention, writes transposed + rounded g_attT ----------------
__global__ void __launch_bounds__(256) attn_kernel() {
    const int wp   = threadIdx.x >> 5;
    const int lane = threadIdx.x & 31;
    const int wgid = blockIdx.x * 8 + wp;
    const int n  = wgid & 2047;
    const int hd = (wgid >> 11) & 3;
    const int sb = wgid >> 13;
    const int y = n >> 5, x = n & 31;

    __shared__ float st[64][9];

    const float* qb = g_q + ((size_t)sb * NTOK + n) * C_DIM + hd * 64;
    const float q0 = qb[lane];
    const float q1 = qb[lane + 32];

    const int ody[13] = {0, 0, 0, 0, 0, -1, -1, -1, 1, 1, 1, -2, 2};
    const int odx[13] = {0,-1, 1,-2, 2,  0, -1,  1, 0,-1, 1,  0, 0};
    float sc[13];
    int   midx[13];

#pragma unroll
    for (int i = 0; i < 13; ++i) {
        int yy = y + ody[i], xx = x + odx[i];
        bool valid = (yy >= 0) && (yy < 64) && (xx >= 0) && (xx < 32);
        int mm = valid ? (yy * 32 + xx) : n;
        midx[i] = valid ? mm : -1;
        const float* kb = g_k + ((size_t)sb * NTOK + mm) * C_DIM + hd * 64;
        float s = q0 * kb[lane] + q1 * kb[lane + 32];
#pragma unroll
        for (int o = 16; o > 0; o >>= 1) s += __shfl_xor_sync(0xffffffffu, s, o);
        sc[i] = valid ? s * 0.125f : -1e30f;
    }

    float mx = -1e30f;
#pragma unroll
    for (int i = 0; i < 13; ++i) mx = fmaxf(mx, sc[i]);
    float ssum = 0.0f;
#pragma unroll
    for (int i = 0; i < 13; ++i) {
        sc[i] = (midx[i] >= 0) ? __expf(sc[i] - mx) : 0.0f;
        ssum += sc[i];
    }
    const float inv = 1.0f / ssum;

    float a0 = 0.0f, a1 = 0.0f;
#pragma unroll
    for (int i = 0; i < 13; ++i) {
        if (midx[i] >= 0) {
            const float* vb = g_v + ((size_t)sb * NTOK + midx[i]) * C_DIM + hd * 64;
            float wgt = sc[i] * inv;
            a0 += wgt * vb[lane];
            a1 += wgt * vb[lane + 32];
        }
    }

    // stage & transpose: st[channel d][token j]
    st[lane][wp]      = a0;
    st[lane + 32][wp] = a1;
    __syncthreads();

    const int base = blockIdx.x * 8;
    const int n0  = base & 2047;
    const int hdb = (base >> 11) & 3;
    const int sbb = base >> 13;
#pragma unroll
    for (int v = 0; v < 2; ++v) {
        int idx = threadIdx.x + 256 * v;
        int d = idx >> 3, j = idx & 7;
        g_attT[((size_t)sbb * C_DIM + hdb * 64 + d) * NTOK + n0 + j] =
            __uint_as_float(f2tf(st[d][j]));
    }
}

// ---------------- K3: out-proj GEMM (tf32 mma, 3-stage cp.async), writes g_ctxT ----------------
__global__ void __launch_bounds__(256) outproj_gemm(const float* __restrict__ out_b) {
    extern __shared__ uint32_t sm[];
    uint32_t* As = sm;
    uint32_t* Bs = sm + 3 * 2176;

    const int co0 = blockIdx.x * 128;
    const int m0  = blockIdx.y * 128;
    const int sb  = blockIdx.z;
    const float* attTB = g_attT + (size_t)sb * C_DIM * NTOK;

    const int t = threadIdx.x;
    const int w = t >> 5, lane = t & 31, quad = lane >> 2, tq = lane & 3;
    const int mw = (w & 1) * 64, nw = (w >> 1) * 32;

    const uint32_t abase0 = sptr(As), bbase0 = sptr(Bs);

    auto fill = [&](int s, int kt) {
        const int c0 = kt * 16;
        const uint32_t ab = abase0 + s * 8704;
        const uint32_t bb = bbase0 + s * 8704;
#pragma unroll
        for (int i = 0; i < 2; ++i) {
            int idx = t + 256 * i;
            int k = idx >> 5, mg = idx & 31;
            CPA16(ab + (k * 136 + mg * 4) * 4, attTB + (size_t)(c0 + k) * NTOK + m0 + mg * 4);
            CPA16(bb + (k * 136 + mg * 4) * 4, g_outwT + (c0 + k) * 256 + co0 + mg * 4);
        }
    };

    float acc[4][4][4];
#pragma unroll
    for (int i = 0; i < 4; ++i)
#pragma unroll
        for (int j = 0; j < 4; ++j)
#pragma unroll
            for (int p = 0; p < 4; ++p) acc[i][j][p] = 0.0f;

    fill(0, 0); CPC();
    fill(1, 1); CPC();

    for (int kt = 0; kt < 16; ++kt) {
        CPW1();
        __syncthreads();
        if (kt + 2 < 16) fill((kt + 2) % 3, kt + 2);
        CPC();
        const uint32_t* A = As + (kt % 3) * 2176;
        const uint32_t* B = Bs + (kt % 3) * 2176;
#pragma unroll
        for (int kb = 0; kb < 2; ++kb) {
            const int k0 = kb * 8;
            uint32_t af[4][4], bf[4][2];
#pragma unroll
            for (int i = 0; i < 4; ++i) {
                af[i][0] = A[(k0 + tq) * 136 + mw + i * 16 + quad];
                af[i][1] = A[(k0 + tq) * 136 + mw + i * 16 + quad + 8];
                af[i][2] = A[(k0 + tq + 4) * 136 + mw + i * 16 + quad];
                af[i][3] = A[(k0 + tq + 4) * 136 + mw + i * 16 + quad + 8];
            }
#pragma unroll
            for (int j = 0; j < 4; ++j) {
                bf[j][0] = B[(k0 + tq) * 136 + nw + j * 8 + quad];
                bf[j][1] = B[(k0 + tq + 4) * 136 + nw + j * 8 + quad];
            }
#pragma unroll
            for (int i = 0; i < 4; ++i)
#pragma unroll
                for (int j = 0; j < 4; ++j)
                    mma8(acc[i][j], af[i], bf[j]);
        }
    }

#pragma unroll
    for (int i = 0; i < 4; ++i) {
        int r0 = m0 + mw + i * 16 + quad;
#pragma unroll
        for (int j = 0; j < 4; ++j) {
            int co = co0 + nw + j * 8 + tq * 2;
            float b0 = out_b[co], b1 = out_b[co + 1];
            float* base = g_ctxT + (size_t)sb * C_DIM * NTOK;
            base[(size_t)co * NTOK + r0]           = acc[i][j][0] + b0;
            base[(size_t)(co + 1) * NTOK + r0]     = acc[i][j][1] + b1;
            base[(size_t)co * NTOK + r0 + 8]       = acc[i][j][2] + b0;
            base[(size_t)(co + 1) * NTOK + r0 + 8] = acc[i][j][3] + b1;
        }
    }
}

// ---------------- K4: fused asym + proj + LN + ReLU ----------------
// BM=128, BN=256, BK=16, 512 thr. A: register path, 2-stage smem, 1 sync/iter.
// B: 3-stage cp.async from g_projwT. Dynamic smem: A 2*2176w, B 3*4224w, red 128*4 float2.
__global__ void __launch_bounds__(512) fused_proj_ln(const float* __restrict__ proj_b,
                                                     const float* __restrict__ ln_g,
                                                     const float* __restrict__ ln_b,
                                                     float* __restrict__ out) {
    extern __shared__ uint32_t sm[];
    uint32_t* As = sm;                       // 2 * 2176
    uint32_t* Bs = sm + 2 * 2176;            // 3 * 4224
    float2*  red = (float2*)(sm + 2 * 2176 + 3 * 4224);   // [128][4]

    const int m0 = blockIdx.y * 128;
    const int sb = blockIdx.z;
    const int side = sb >> 3, b = sb & 7;
    const float* featRB = g_featR + (size_t)b * (C_DIM * 4096);
    const float* ctxTB  = g_ctxT + (size_t)sb * C_DIM * NTOK;

    const int t = threadIdx.x;
    const int w = t >> 5, lane = t & 31, quad = lane >> 2, tq = lane & 3;
    const int wm = w & 3, nwi = w >> 2;
    const int mw = wm * 32, nwcol = nwi * 64;

    const int amm = t & 127, akb = t >> 7;   // fills k = akb + 4*i, i<4
    const int lm = m0 + amm;
    const int ly = lm >> 5, lx = lm & 31;
    const int qoff = ly * 64 + (side ? 32 + lx : lx);

    const uint32_t bbase0 = sptr(Bs);

    auto fillB = [&](int s, int kt) {
        const int j0 = kt * 16;
        const uint32_t bb = bbase0 + s * 16896;
#pragma unroll
        for (int i = 0; i < 2; ++i) {
            int idx = t + 512 * i;
            int k = idx >> 6, jg = idx & 63;
            CPA16(bb + (k * 264 + jg * 4) * 4, g_projwT + (j0 + k) * 256 + jg * 4);
        }
    };

    float acc[2][8][4];
#pragma unroll
    for (int i = 0; i < 2; ++i)
#pragma unroll
        for (int j = 0; j < 8; ++j)
#pragma unroll
            for (int p = 0; p < 4; ++p) acc[i][j][p] = 0.0f;

    fillB(0, 0); CPC();
    fillB(1, 1); CPC();

    float rq[4], rc[4];
    // A(0): part 0 (pure q)
#pragma unroll
    for (int i = 0; i < 4; ++i) {
        rq[i] = featRB[(size_t)(akb + 4 * i) * 4096 + qoff];
        As[(akb + 4 * i) * 136 + amm] = __float_as_uint(rq[i]);   // already rounded
        rc[i] = 0.0f;
    }

    for (int kt = 0; kt < 64; ++kt) {
        CPW1();
        __syncthreads();
        if (kt + 2 < 64) fillB((kt + 2) % 3, kt + 2);
        CPC();

        // LDG A-data for kt+1
        int np = (kt + 1) >> 4;
        if (kt < 63) {
#pragma unroll
            for (int i = 0; i < 4; ++i) {
                int jc = ((kt + 1) * 16 + akb + 4 * i) & 255;
                if (np != 1) rq[i] = featRB[(size_t)jc * 4096 + qoff];
                if (np != 0) rc[i] = ctxTB[(size_t)jc * NTOK + lm];
            }
        }

        // compute stage kt
        const uint32_t* A = As + (kt & 1) * 2176;
        const uint32_t* B = Bs + (kt % 3) * 4224;
#pragma unroll
        for (int kb = 0; kb < 2; ++kb) {
            const int k0 = kb * 8;
            uint32_t af[2][4], bf[8][2];
#pragma unroll
            for (int i = 0; i < 2; ++i) {
                af[i][0] = A[(k0 + tq) * 136 + mw + i * 16 + quad];
                af[i][1] = A[(k0 + tq) * 136 + mw + i * 16 + quad + 8];
                af[i][2] = A[(k0 + tq + 4) * 136 + mw + i * 16 + quad];
                af[i][3] = A[(k0 + tq + 4) * 136 + mw + i * 16 + quad + 8];
            }
#pragma unroll
            for (int j = 0; j < 8; ++j) {
                bf[j][0] = B[(k0 + tq) * 264 + nwcol + j * 8 + quad];
                bf[j][1] = B[(k0 + tq + 4) * 264 + nwcol + j * 8 + quad];
            }
#pragma unroll
            for (int i = 0; i < 2; ++i)
#pragma unroll
                for (int j = 0; j < 8; ++j)
                    mma8(acc[i][j], af[i], bf[j]);
        }

        // STS A(kt+1) into the other stage (safe: all threads passed this iter's barrier)
        if (kt < 63) {
            uint32_t* An = As + ((kt + 1) & 1) * 2176;
#pragma unroll
            for (int i = 0; i < 4; ++i) {
                float v;
                if (np == 0)      v = rq[i];
                else if (np == 1) v = rc[i];
                else if (np == 2) v = fabsf(rq[i] - rc[i]);
                else              v = rq[i] * rc[i];
                An[(akb + 4 * i) * 136 + amm] = f2tf(v);
            }
        }
    }

    // ---- epilogue: +bias, LN(256), relu, transposed scatter ----
#pragma unroll
    for (int j = 0; j < 8; ++j) {
        int co = nwcol + j * 8 + tq * 2;
        float2 pb = *(const float2*)&proj_b[co];
#pragma unroll
        for (int i = 0; i < 2; ++i) {
            acc[i][j][0] += pb.x; acc[i][j][1] += pb.y;
            acc[i][j][2] += pb.x; acc[i][j][3] += pb.y;
        }
    }

    __syncthreads();   // A/B stages done; reuse smem region for reductions is disjoint (red)
#pragma unroll
    for (int i = 0; i < 2; ++i)
#pragma unroll
        for (int u = 0; u < 2; ++u) {
            float s1 = 0.0f, s2 = 0.0f;
#pragma unroll
            for (int j = 0; j < 8; ++j) {
                float x0 = acc[i][j][2 * u], x1 = acc[i][j][2 * u + 1];
                s1 += x0 + x1; s2 += x0 * x0 + x1 * x1;
            }
            s1 += __shfl_xor_sync(0xffffffffu, s1, 1);
            s2 += __shfl_xor_sync(0xffffffffu, s2, 1);
            s1 += __shfl_xor_sync(0xffffffffu, s1, 2);
            s2 += __shfl_xor_sync(0xffffffffu, s2, 2);
            if (tq == 0) {
                int r = mw + i * 16 + u * 8 + quad;
                red[r * 4 + nwi] = make_float2(s1, s2);
            }
        }
    __syncthreads();

#pragma unroll
    for (int i = 0; i < 2; ++i)
#pragma unroll
        for (int u = 0; u < 2; ++u) {
            int r = mw + i * 16 + u * 8 + quad;
            float s1 = 0.0f, s2 = 0.0f;
#pragma unroll
            for (int p = 0; p < 4; ++p) { float2 v = red[r * 4 + p]; s1 += v.x; s2 += v.y; }
            float mu   = s1 * (1.0f / 256.0f);
            float var  = s2 * (1.0f / 256.0f) - mu * mu;
            float rstd = rsqrtf(var + 1e-5f);

            int grow = m0 + r;
            int y = grow >> 5, x = grow & 31;
            int xg = side ? (32 + x) : x;
            size_t obase = (size_t)b * C_DIM * 4096 + y * 64 + xg;
#pragma unroll
            for (int j = 0; j < 8; ++j) {
                int co = nwcol + j * 8 + tq * 2;
                float g0 = ln_g[co], g1 = ln_g[co + 1];
                float l0 = ln_b[co], l1 = ln_b[co + 1];
                float v0 = fmaxf((acc[i][j][2 * u]     - mu) * rstd * g0 + l0, 0.0f);
                float v1 = fmaxf((acc[i][j][2 * u + 1] - mu) * rstd * g1 + l1, 0.0f);
                out[obase + (size_t)co * 4096]       = v0;
                out[obase + (size_t)(co + 1) * 4096] = v1;
            }
        }
}

// ---------------- launch ----------------
extern "C" void kernel_launch(void* const* d_in, const int* in_sizes, int n_in,
                              void* d_out, int out_size) {
    const float* feat   = (const float*)d_in[0];
    const float* in_w   = (const float*)d_in[1];
    const float* in_b   = (const float*)d_in[2];
    const float* out_w  = (const float*)d_in[3];
    const float* out_b  = (const float*)d_in[4];
    const float* proj_w = (const float*)d_in[5];
    const float* proj_b = (const float*)d_in[6];
    const float* ln_g   = (const float*)d_in[7];
    const float* ln_b   = (const float*)d_in[8];
    float* out = (float*)d_out;

    const int QKV_SMEM = 3 * 2176 * 2 * 4;                         // 52224 B
    const int K4_SMEM  = (2 * 2176 + 3 * 4224) * 4 + 128 * 4 * 8;  // 72192 B
    cudaFuncSetAttribute(qkv_gemm,      cudaFuncAttributeMaxDynamicSharedMemorySize, QKV_SMEM);
    cudaFuncSetAttribute(outproj_gemm,  cudaFuncAttributeMaxDynamicSharedMemorySize, QKV_SMEM);
    cudaFuncSetAttribute(fused_proj_ln, cudaFuncAttributeMaxDynamicSharedMemorySize, K4_SMEM);

    transpose_weights<<<1024, 256>>>(in_w, out_w, proj_w);
    round_feat<<<8192, 256>>>(feat);
    qkv_gemm<<<dim3(6, 16, 16), 256, QKV_SMEM>>>(in_b);
    attn_kernel<<<16384, 256>>>();
    outproj_gemm<<<dim3(2, 16, 16), 256, QKV_SMEM>>>(out_b);
    fused_proj_ln<<<dim3(1, 16, 16), 512, K4_SMEM>>>(proj_b, ln_g, ln_b, out);
}

// round 11
// speedup vs baseline: 1.3210x; 1.2375x over previous
#include <cuda_runtime.h>
#include <cstdint>
#include <math.h>

#define C_DIM 256
#define NTOK 2048          // 64 * 32 tokens per side per batch
#define SB_COUNT 16        // side(2) * batch(8)

// ---------------- scratch (static device globals; no allocation) ----------------
__device__ float g_featR[8 * C_DIM * 4096];             // tf32-rounded feat (same layout)
__device__ float g_qT[SB_COUNT * C_DIM * NTOK];         // q transposed [sb][c][n]
__device__ float g_kT[SB_COUNT * C_DIM * NTOK];
__device__ float g_vT[SB_COUNT * C_DIM * NTOK];
__device__ float g_attT[SB_COUNT * C_DIM * NTOK];       // attention ctx, transposed + tf32-rounded
__device__ float g_ctxT[SB_COUNT * C_DIM * NTOK];       // out-proj result, transposed [sb][c][n]
__device__ float g_inwT[C_DIM * 768];                   // in_w^T  (tf32-rounded)
__device__ float g_outwT[C_DIM * C_DIM];                // out_w^T (tf32-rounded)
__device__ float g_projwT[1024 * C_DIM];                // proj_w^T(tf32-rounded)

// ---------------- helpers ----------------
__device__ __forceinline__ uint32_t f2tf(float x) {
    uint32_t u; asm("cvt.rna.tf32.f32 %0, %1;" : "=r"(u) : "f"(x)); return u;
}
__device__ __forceinline__ void mma8(float* c, const uint32_t* a, const uint32_t* b) {
    asm volatile("mma.sync.aligned.m16n8k8.row.col.f32.tf32.tf32.f32 "
        "{%0,%1,%2,%3}, {%4,%5,%6,%7}, {%8,%9}, {%0,%1,%2,%3};"
        : "+f"(c[0]), "+f"(c[1]), "+f"(c[2]), "+f"(c[3])
        : "r"(a[0]), "r"(a[1]), "r"(a[2]), "r"(a[3]), "r"(b[0]), "r"(b[1]));
}
__device__ __forceinline__ uint32_t sptr(const void* p) {
    return (uint32_t)__cvta_generic_to_shared(p);
}
#define CPA4(d, s)  asm volatile("cp.async.ca.shared.global [%0], [%1], 4;"  :: "r"(d), "l"(s))
#define CPA16(d, s) asm volatile("cp.async.cg.shared.global [%0], [%1], 16;" :: "r"(d), "l"(s))
#define CPC()  asm volatile("cp.async.commit_group;")
#define CPW1() asm volatile("cp.async.wait_group 1;")
#define CPW0() asm volatile("cp.async.wait_group 0;")

// ---------------- K0a: transpose + tf32-round weights ----------------
__global__ void transpose_weights(const float* __restrict__ in_w,
                                  const float* __restrict__ out_w,
                                  const float* __restrict__ proj_w) {
    int i = blockIdx.x * blockDim.x + threadIdx.x;
    if (i < 768 * 256) { int co = i >> 8;  int c = i & 255;  g_inwT[c * 768 + co]  = __uint_as_float(f2tf(in_w[i])); }
    if (i < 256 * 256) { int co = i >> 8;  int c = i & 255;  g_outwT[c * 256 + co] = __uint_as_float(f2tf(out_w[i])); }
    if (i < 256 * 1024){ int co = i >> 10; int j = i & 1023; g_projwT[j * 256 + co] = __uint_as_float(f2tf(proj_w[i])); }
}

// ---------------- K0b: tf32-round feat ----------------
__global__ void round_feat(const float* __restrict__ feat) {
    int i = blockIdx.x * blockDim.x + threadIdx.x;   // float4 index
    float4 v = ((const float4*)feat)[i];
    v.x = __uint_as_float(f2tf(v.x)); v.y = __uint_as_float(f2tf(v.y));
    v.z = __uint_as_float(f2tf(v.z)); v.w = __uint_as_float(f2tf(v.w));
    ((float4*)g_featR)[i] = v;
}

// ---------------- K1: QKV GEMM (tf32 mma, 3-stage cp.async) ----------------
// BM=128 BN=128 BK=16, 256 thr, warp tile 64x32. Writes q/k/v TRANSPOSED [sb][c][n].
__global__ void __launch_bounds__(256) qkv_gemm(const float* __restrict__ in_b) {
    extern __shared__ uint32_t sm[];
    uint32_t* As = sm;              // 3 stages * 2176 words
    uint32_t* Bs = sm + 3 * 2176;

    const int co0 = blockIdx.x * 128;
    const int m0  = blockIdx.y * 128;
    const int sb  = blockIdx.z;
    const int side = sb >> 3, b = sb & 7;
    const bool is_q = (co0 < 256);
    const float* featRB = g_featR + (size_t)b * (C_DIM * 4096);

    const int t = threadIdx.x;
    const int w = t >> 5, lane = t & 31, quad = lane >> 2, tq = lane & 3;
    const int mw = (w & 1) * 64, nw = (w >> 1) * 32;

    const int mm = t & 127;
    const int m  = m0 + mm;
    const int yq = m >> 5, xq = m & 31;
    const int colg = is_q ? (side ? 32 + xq : xq) : (side ? 31 - xq : 63 - xq);
    const int aoff = yq * 64 + colg;
    const int kb0 = t >> 7;   // fills k = kb0 + 2*i

    const uint32_t abase0 = sptr(As), bbase0 = sptr(Bs);

    auto fill = [&](int s, int kt) {
        const int c0 = kt * 16;
        const uint32_t ab = abase0 + s * 8704;
        const uint32_t bb = bbase0 + s * 8704;
#pragma unroll
        for (int i = 0; i < 8; ++i) {
            int k = kb0 + 2 * i;
            CPA4(ab + (k * 136 + mm) * 4, featRB + (size_t)(c0 + k) * 4096 + aoff);
        }
#pragma unroll
        for (int i = 0; i < 2; ++i) {
            int idx = t + 256 * i;
            int k = idx >> 5, jg = idx & 31;
            CPA16(bb + (k * 136 + jg * 4) * 4, g_inwT + (c0 + k) * 768 + co0 + jg * 4);
        }
    };

    float acc[4][4][4];
#pragma unroll
    for (int i = 0; i < 4; ++i)
#pragma unroll
        for (int j = 0; j < 4; ++j)
#pragma unroll
            for (int p = 0; p < 4; ++p) acc[i][j][p] = 0.0f;

    fill(0, 0); CPC();
    fill(1, 1); CPC();

    for (int kt = 0; kt < 16; ++kt) {
        CPW1();
        __syncthreads();
        if (kt + 2 < 16) fill((kt + 2) % 3, kt + 2);
        CPC();
        const uint32_t* A = As + (kt % 3) * 2176;
        const uint32_t* B = Bs + (kt % 3) * 2176;
#pragma unroll
        for (int kb = 0; kb < 2; ++kb) {
            const int k0 = kb * 8;
            uint32_t af[4][4], bf[4][2];
#pragma unroll
            for (int i = 0; i < 4; ++i) {
                af[i][0] = A[(k0 + tq) * 136 + mw + i * 16 + quad];
                af[i][1] = A[(k0 + tq) * 136 + mw + i * 16 + quad + 8];
                af[i][2] = A[(k0 + tq + 4) * 136 + mw + i * 16 + quad];
                af[i][3] = A[(k0 + tq + 4) * 136 + mw + i * 16 + quad + 8];
            }
#pragma unroll
            for (int j = 0; j < 4; ++j) {
                bf[j][0] = B[(k0 + tq) * 136 + nw + j * 8 + quad];
                bf[j][1] = B[(k0 + tq + 4) * 136 + nw + j * 8 + quad];
            }
#pragma unroll
            for (int i = 0; i < 4; ++i)
#pragma unroll
                for (int j = 0; j < 4; ++j)
                    mma8(acc[i][j], af[i], bf[j]);
        }
    }

    // transposed epilogue: dst[cl][row]
#pragma unroll
    for (int i = 0; i < 4; ++i) {
        int r0 = m0 + mw + i * 16 + quad;
#pragma unroll
        for (int j = 0; j < 4; ++j) {
            int co = co0 + nw + j * 8 + tq * 2;
            float b0 = in_b[co], b1 = in_b[co + 1];
            float* dst = (co < 256) ? g_qT : ((co < 512) ? g_kT : g_vT);
            int cl = co & 255;
            float* base0 = dst + ((size_t)sb * C_DIM + cl) * NTOK;
            float* base1 = base0 + NTOK;
            base0[r0]     = acc[i][j][0] + b0;
            base1[r0]     = acc[i][j][1] + b1;
            base0[r0 + 8] = acc[i][j][2] + b0;
            base1[r0 + 8] = acc[i][j][3] + b1;
        }
    }
}

// ---------------- K2: sparse attention v2 (thread-per-token, smem tiles) ----------------
// Block: 128 thr = 4 y-rows of tokens, one (sb, head). Tile: 8 y-rows (halo 2).
// k/v stream through 2 buffers x [16 ch][264] smem chunks via cp.async.
__global__ void __launch_bounds__(128, 4) attn_kernel() {
    __shared__ float smk[2][16 * 264];

    const int t = threadIdx.x;
    const int yblk = blockIdx.x;     // 0..15 (4 rows each)
    const int hd   = blockIdx.y;     // 0..3
    const int sb   = blockIdx.z;     // 0..15
    const int n0 = yblk * 128;
    const int n  = n0 + t;
    const int y = n >> 5, x = n & 31;
    const int lt = 64 + t;           // local token index within tile (tile starts at n0-64)

    const float* qTB = g_qT + ((size_t)sb * C_DIM + hd * 64) * NTOK;
    const float* kTB = g_kT + ((size_t)sb * C_DIM + hd * 64) * NTOK;
    const float* vTB = g_vT + ((size_t)sb * C_DIM + hd * 64) * NTOK;

    // zero pad columns (cols [0,4) and [260,264) of each of 16 rows, both buffers)
    for (int i = t; i < 256; i += 128) {
        int buf = i >> 7, rem = i & 127;
        int row = rem >> 3, c8 = rem & 7;
        int col = (c8 < 4) ? c8 : (256 + c8);
        smk[buf][row * 264 + col] = 0.0f;
    }

    const int ody[13] = {0, 0, 0, 0, 0, -1, -1, -1, 1, 1, 1, -2, 2};
    const int odx[13] = {0,-1, 1,-2, 2,  0, -1,  1, 0,-1, 1,  0, 0};

    bool va[13];
#pragma unroll
    for (int i = 0; i < 13; ++i) {
        int yy = y + ody[i], xx = x + odx[i];
        va[i] = (yy >= 0) && (yy < 64) && (xx >= 0) && (xx < 32);
    }

    // q in registers (reused 13x per channel; later reused as output accumulator)
    float qa[64];
#pragma unroll
    for (int d = 0; d < 64; ++d) qa[d] = qTB[(size_t)d * NTOK + n];

    const int y0m2 = (n0 >> 5) - 2;
    auto fill = [&](int buf, int c) {
        const float* src = (c < 4) ? (kTB + (size_t)(c * 16) * NTOK)
                                   : (vTB + (size_t)((c - 4) * 16) * NTOK);
        uint32_t dst = sptr(&smk[buf][0]);
#pragma unroll
        for (int i = 0; i < 8; ++i) {
            int idx = t + 128 * i;
            int d = idx >> 6, jj = idx & 63;
            int yy = y0m2 + (jj >> 3);
            int yc = min(max(yy, 0), 63);
            int sn = yc * 32 + (jj & 7) * 4;
            CPA16(dst + (d * 264 + 4 + jj * 4) * 4, src + (size_t)d * NTOK + sn);
        }
    };

    float sc[13];
#pragma unroll
    for (int i = 0; i < 13; ++i) sc[i] = 0.0f;

    fill(0, 0); CPC();

#pragma unroll
    for (int c = 0; c < 8; ++c) {
        if (c < 7) { fill((c + 1) & 1, c + 1); CPC(); CPW1(); }
        else       { CPW0(); }
        __syncthreads();
        const float* buf = smk[c & 1];
        if (c < 4) {
            // score accumulation for channels [c*16, c*16+16)
#pragma unroll
            for (int dd = 0; dd < 16; ++dd) {
                float qv = qa[c * 16 + dd];
                const float* base = buf + dd * 264 + 4 + lt;
#pragma unroll
                for (int i = 0; i < 13; ++i)
                    sc[i] += qv * base[ody[i] * 32 + odx[i]];
            }
            if (c == 3) {
                // softmax over 13 (masked)
                float mx = -1e30f;
#pragma unroll
                for (int i = 0; i < 13; ++i) {
                    sc[i] = va[i] ? sc[i] * 0.125f : -1e30f;
                    mx = fmaxf(mx, sc[i]);
                }
                float ssum = 0.0f;
#pragma unroll
                for (int i = 0; i < 13; ++i) {
                    sc[i] = va[i] ? __expf(sc[i] - mx) : 0.0f;
                    ssum += sc[i];
                }
                float inv = 1.0f / ssum;
#pragma unroll
                for (int i = 0; i < 13; ++i) sc[i] *= inv;
            }
        } else {
            // weighted V accumulation; overwrite qa (q no longer needed)
#pragma unroll
            for (int dd = 0; dd < 16; ++dd) {
                const float* base = buf + dd * 264 + 4 + lt;
                float a = 0.0f;
#pragma unroll
                for (int i = 0; i < 13; ++i)
                    a += sc[i] * base[ody[i] * 32 + odx[i]];
                qa[(c - 4) * 16 + dd] = a;
            }
        }
        __syncthreads();
    }

    // store transposed + tf32-rounded, coalesced over n
    float* oB = g_attT + ((size_t)sb * C_DIM + hd * 64) * NTOK + n;
#pragma unroll
    for (int d = 0; d < 64; ++d)
        oB[(size_t)d * NTOK] = __uint_as_float(f2tf(qa[d]));
}

// ---------------- K3: out-proj GEMM (tf32 mma, 3-stage cp.async), writes g_ctxT ----------------
__global__ void __launch_bounds__(256) outproj_gemm(const float* __restrict__ out_b) {
    extern __shared__ uint32_t sm[];
    uint32_t* As = sm;
    uint32_t* Bs = sm + 3 * 2176;

    const int co0 = blockIdx.x * 128;
    const int m0  = blockIdx.y * 128;
    const int sb  = blockIdx.z;
    const float* attTB = g_attT + (size_t)sb * C_DIM * NTOK;

    const int t = threadIdx.x;
    const int w = t >> 5, lane = t & 31, quad = lane >> 2, tq = lane & 3;
    const int mw = (w & 1) * 64, nw = (w >> 1) * 32;

    const uint32_t abase0 = sptr(As), bbase0 = sptr(Bs);

    auto fill = [&](int s, int kt) {
        const int c0 = kt * 16;
        const uint32_t ab = abase0 + s * 8704;
        const uint32_t bb = bbase0 + s * 8704;
#pragma unroll
        for (int i = 0; i < 2; ++i) {
            int idx = t + 256 * i;
            int k = idx >> 5, mg = idx & 31;
            CPA16(ab + (k * 136 + mg * 4) * 4, attTB + (size_t)(c0 + k) * NTOK + m0 + mg * 4);
            CPA16(bb + (k * 136 + mg * 4) * 4, g_outwT + (c0 + k) * 256 + co0 + mg * 4);
        }
    };

    float acc[4][4][4];
#pragma unroll
    for (int i = 0; i < 4; ++i)
#pragma unroll
        for (int j = 0; j < 4; ++j)
#pragma unroll
            for (int p = 0; p < 4; ++p) acc[i][j][p] = 0.0f;

    fill(0, 0); CPC();
    fill(1, 1); CPC();

    for (int kt = 0; kt < 16; ++kt) {
        CPW1();
        __syncthreads();
        if (kt + 2 < 16) fill((kt + 2) % 3, kt + 2);
        CPC();
        const uint32_t* A = As + (kt % 3) * 2176;
        const uint32_t* B = Bs + (kt % 3) * 2176;
#pragma unroll
        for (int kb = 0; kb < 2; ++kb) {
            const int k0 = kb * 8;
            uint32_t af[4][4], bf[4][2];
#pragma unroll
            for (int i = 0; i < 4; ++i) {
                af[i][0] = A[(k0 + tq) * 136 + mw + i * 16 + quad];
                af[i][1] = A[(k0 + tq) * 136 + mw + i * 16 + quad + 8];
                af[i][2] = A[(k0 + tq + 4) * 136 + mw + i * 16 + quad];
                af[i][3] = A[(k0 + tq + 4) * 136 + mw + i * 16 + quad + 8];
            }
#pragma unroll
            for (int j = 0; j < 4; ++j) {
                bf[j][0] = B[(k0 + tq) * 136 + nw + j * 8 + quad];
                bf[j][1] = B[(k0 + tq + 4) * 136 + nw + j * 8 + quad];
            }
#pragma unroll
            for (int i = 0; i < 4; ++i)
#pragma unroll
                for (int j = 0; j < 4; ++j)
                    mma8(acc[i][j], af[i], bf[j]);
        }
    }

#pragma unroll
    for (int i = 0; i < 4; ++i) {
        int r0 = m0 + mw + i * 16 + quad;
#pragma unroll
        for (int j = 0; j < 4; ++j) {
            int co = co0 + nw + j * 8 + tq * 2;
            float b0 = out_b[co], b1 = out_b[co + 1];
            float* base = g_ctxT + (size_t)sb * C_DIM * NTOK;
            base[(size_t)co * NTOK + r0]           = acc[i][j][0] + b0;
            base[(size_t)(co + 1) * NTOK + r0]     = acc[i][j][1] + b1;
            base[(size_t)co * NTOK + r0 + 8]       = acc[i][j][2] + b0;
            base[(size_t)(co + 1) * NTOK + r0 + 8] = acc[i][j][3] + b1;
        }
    }
}

// ---------------- K4: fused asym + proj + LN + ReLU ----------------
// BM=128, BN=256, BK=16, 512 thr. A: register path, 2-stage smem, 1 sync/iter.
// B: 3-stage cp.async from g_projwT.
__global__ void __launch_bounds__(512) fused_proj_ln(const float* __restrict__ proj_b,
                                                     const float* __restrict__ ln_g,
                                                     const float* __restrict__ ln_b,
                                                     float* __restrict__ out) {
    extern __shared__ uint32_t sm[];
    uint32_t* As = sm;                       // 2 * 2176
    uint32_t* Bs = sm + 2 * 2176;            // 3 * 4224
    float2*  red = (float2*)(sm + 2 * 2176 + 3 * 4224);   // [128][4]

    const int m0 = blockIdx.y * 128;
    const int sb = blockIdx.z;
    const int side = sb >> 3, b = sb & 7;
    const float* featRB = g_featR + (size_t)b * (C_DIM * 4096);
    const float* ctxTB  = g_ctxT + (size_t)sb * C_DIM * NTOK;

    const int t = threadIdx.x;
    const int w = t >> 5, lane = t & 31, quad = lane >> 2, tq = lane & 3;
    const int wm = w & 3, nwi = w >> 2;
    const int mw = wm * 32, nwcol = nwi * 64;

    const int amm = t & 127, akb = t >> 7;   // fills k = akb + 4*i, i<4
    const int lm = m0 + amm;
    const int ly = lm >> 5, lx = lm & 31;
    const int qoff = ly * 64 + (side ? 32 + lx : lx);

    const uint32_t bbase0 = sptr(Bs);

    auto fillB = [&](int s, int kt) {
        const int j0 = kt * 16;
        const uint32_t bb = bbase0 + s * 16896;
#pragma unroll
        for (int i = 0; i < 2; ++i) {
            int idx = t + 512 * i;
            int k = idx >> 6, jg = idx & 63;
            CPA16(bb + (k * 264 + jg * 4) * 4, g_projwT + (j0 + k) * 256 + jg * 4);
        }
    };

    float acc[2][8][4];
#pragma unroll
    for (int i = 0; i < 2; ++i)
#pragma unroll
        for (int j = 0; j < 8; ++j)
#pragma unroll
            for (int p = 0; p < 4; ++p) acc[i][j][p] = 0.0f;

    fillB(0, 0); CPC();
    fillB(1, 1); CPC();

    float rq[4], rc[4];
#pragma unroll
    for (int i = 0; i < 4; ++i) {
        rq[i] = featRB[(size_t)(akb + 4 * i) * 4096 + qoff];
        As[(akb + 4 * i) * 136 + amm] = __float_as_uint(rq[i]);   // already rounded
        rc[i] = 0.0f;
    }

    for (int kt = 0; kt < 64; ++kt) {
        CPW1();
        __syncthreads();
        if (kt + 2 < 64) fillB((kt + 2) % 3, kt + 2);
        CPC();

        int np = (kt + 1) >> 4;
        if (kt < 63) {
#pragma unroll
            for (int i = 0; i < 4; ++i) {
                int jc = ((kt + 1) * 16 + akb + 4 * i) & 255;
                if (np != 1) rq[i] = featRB[(size_t)jc * 4096 + qoff];
                if (np != 0) rc[i] = ctxTB[(size_t)jc * NTOK + lm];
            }
        }

        const uint32_t* A = As + (kt & 1) * 2176;
        const uint32_t* B = Bs + (kt % 3) * 4224;
#pragma unroll
        for (int kb = 0; kb < 2; ++kb) {
            const int k0 = kb * 8;
            uint32_t af[2][4], bf[8][2];
#pragma unroll
            for (int i = 0; i < 2; ++i) {
                af[i][0] = A[(k0 + tq) * 136 + mw + i * 16 + quad];
                af[i][1] = A[(k0 + tq) * 136 + mw + i * 16 + quad + 8];
                af[i][2] = A[(k0 + tq + 4) * 136 + mw + i * 16 + quad];
                af[i][3] = A[(k0 + tq + 4) * 136 + mw + i * 16 + quad + 8];
            }
#pragma unroll
            for (int j = 0; j < 8; ++j) {
                bf[j][0] = B[(k0 + tq) * 264 + nwcol + j * 8 + quad];
                bf[j][1] = B[(k0 + tq + 4) * 264 + nwcol + j * 8 + quad];
            }
#pragma unroll
            for (int i = 0; i < 2; ++i)
#pragma unroll
                for (int j = 0; j < 8; ++j)
                    mma8(acc[i][j], af[i], bf[j]);
        }

        if (kt < 63) {
            uint32_t* An = As + ((kt + 1) & 1) * 2176;
#pragma unroll
            for (int i = 0; i < 4; ++i) {
                float v;
                if (np == 0)      v = rq[i];
                else if (np == 1) v = rc[i];
                else if (np == 2) v = fabsf(rq[i] - rc[i]);
                else              v = rq[i] * rc[i];
                An[(akb + 4 * i) * 136 + amm] = f2tf(v);
            }
        }
    }

    // ---- epilogue: +bias, LN(256), relu, transposed scatter ----
#pragma unroll
    for (int j = 0; j < 8; ++j) {
        int co = nwcol + j * 8 + tq * 2;
        float2 pb = *(const float2*)&proj_b[co];
#pragma unroll
        for (int i = 0; i < 2; ++i) {
            acc[i][j][0] += pb.x; acc[i][j][1] += pb.y;
            acc[i][j][2] += pb.x; acc[i][j][3] += pb.y;
        }
    }

    __syncthreads();
#pragma unroll
    for (int i = 0; i < 2; ++i)
#pragma unroll
        for (int u = 0; u < 2; ++u) {
            float s1 = 0.0f, s2 = 0.0f;
#pragma unroll
            for (int j = 0; j < 8; ++j) {
                float x0 = acc[i][j][2 * u], x1 = acc[i][j][2 * u + 1];
                s1 += x0 + x1; s2 += x0 * x0 + x1 * x1;
            }
            s1 += __shfl_xor_sync(0xffffffffu, s1, 1);
            s2 += __shfl_xor_sync(0xffffffffu, s2, 1);
            s1 += __shfl_xor_sync(0xffffffffu, s1, 2);
            s2 += __shfl_xor_sync(0xffffffffu, s2, 2);
            if (tq == 0) {
                int r = mw + i * 16 + u * 8 + quad;
                red[r * 4 + nwi] = make_float2(s1, s2);
            }
        }
    __syncthreads();

#pragma unroll
    for (int i = 0; i < 2; ++i)
#pragma unroll
        for (int u = 0; u < 2; ++u) {
            int r = mw + i * 16 + u * 8 + quad;
            float s1 = 0.0f, s2 = 0.0f;
#pragma unroll
            for (int p = 0; p < 4; ++p) { float2 v = red[r * 4 + p]; s1 += v.x; s2 += v.y; }
            float mu   = s1 * (1.0f / 256.0f);
            float var  = s2 * (1.0f / 256.0f) - mu * mu;
            float rstd = rsqrtf(var + 1e-5f);

            int grow = m0 + r;
            int y = grow >> 5, x = grow & 31;
            int xg = side ? (32 + x) : x;
            size_t obase = (size_t)b * C_DIM * 4096 + y * 64 + xg;
#pragma unroll
            for (int j = 0; j < 8; ++j) {
                int co = nwcol + j * 8 + tq * 2;
                float g0 = ln_g[co], g1 = ln_g[co + 1];
                float l0 = ln_b[co], l1 = ln_b[co + 1];
                float v0 = fmaxf((acc[i][j][2 * u]     - mu) * rstd * g0 + l0, 0.0f);
                float v1 = fmaxf((acc[i][j][2 * u + 1] - mu) * rstd * g1 + l1, 0.0f);
                out[obase + (size_t)co * 4096]       = v0;
                out[obase + (size_t)(co + 1) * 4096] = v1;
            }
        }
}

// ---------------- launch ----------------
extern "C" void kernel_launch(void* const* d_in, const int* in_sizes, int n_in,
                              void* d_out, int out_size) {
    const float* feat   = (const float*)d_in[0];
    const float* in_w   = (const float*)d_in[1];
    const float* in_b   = (const float*)d_in[2];
    const float* out_w  = (const float*)d_in[3];
    const float* out_b  = (const float*)d_in[4];
    const float* proj_w = (const float*)d_in[5];
    const float* proj_b = (const float*)d_in[6];
    const float* ln_g   = (const float*)d_in[7];
    const float* ln_b   = (const float*)d_in[8];
    float* out = (float*)d_out;

    const int QKV_SMEM = 3 * 2176 * 2 * 4;                         // 52224 B
    const int K4_SMEM  = (2 * 2176 + 3 * 4224) * 4 + 128 * 4 * 8;  // 72192 B
    cudaFuncSetAttribute(qkv_gemm,      cudaFuncAttributeMaxDynamicSharedMemorySize, QKV_SMEM);
    cudaFuncSetAttribute(outproj_gemm,  cudaFuncAttributeMaxDynamicSharedMemorySize, QKV_SMEM);
    cudaFuncSetAttribute(fused_proj_ln, cudaFuncAttributeMaxDynamicSharedMemorySize, K4_SMEM);

    transpose_weights<<<1024, 256>>>(in_w, out_w, proj_w);
    round_feat<<<8192, 256>>>(feat);
    qkv_gemm<<<dim3(6, 16, 16), 256, QKV_SMEM>>>(in_b);
    attn_kernel<<<dim3(16, 4, 16), 128>>>();
    outproj_gemm<<<dim3(2, 16, 16), 256, QKV_SMEM>>>(out_b);
    fused_proj_ln<<<dim3(1, 16, 16), 512, K4_SMEM>>>(proj_b, ln_g, ln_b, out);
}